// round 6
// baseline (speedup 1.0000x reference)
#include <cuda_runtime.h>

#define NN 4096
#define NJC 37                // j-chunks (grid.y) -> 16*37 = 592 blocks = 4/SM even wave
#define JCH 112               // j's per chunk (37*112 = 4144 >= 4096, rest sentinels)
#define NDUO (JCH / 2)        // 56 packed duos per chunk
#define IBLK 256
#define NBLK (16 * NJC)       // 592 total blocks
#define EPSF 1e-8f

// Deterministic per-chunk partial repulsive forces: g_rf[chunk][i]
__device__ float2 g_rf[NJC][NN];
// Single-kernel grid sync (threadFenceReduction pattern). Zero-init; every
// invocation resets them to 0 before exiting -> deterministic replays.
__device__ unsigned g_arrive;
__device__ unsigned g_done;

typedef unsigned long long u64;

// ---- packed f32x2 helpers (sm_103a) --------------------------------------
__device__ __forceinline__ u64 pk2(float lo, float hi) {
    u64 r; asm("mov.b64 %0, {%1, %2};" : "=l"(r) : "f"(lo), "f"(hi)); return r;
}
__device__ __forceinline__ void upk2(u64 v, float& lo, float& hi) {
    asm("mov.b64 {%0, %1}, %2;" : "=f"(lo), "=f"(hi) : "l"(v));
}
__device__ __forceinline__ u64 add2(u64 a, u64 b) {
    u64 r; asm("add.rn.f32x2 %0, %1, %2;" : "=l"(r) : "l"(a), "l"(b)); return r;
}
__device__ __forceinline__ u64 mul2(u64 a, u64 b) {
    u64 r; asm("mul.rn.f32x2 %0, %1, %2;" : "=l"(r) : "l"(a), "l"(b)); return r;
}
__device__ __forceinline__ u64 fma2(u64 a, u64 b, u64 c) {
    u64 r; asm("fma.rn.f32x2 %0, %1, %2, %3;" : "=l"(r) : "l"(a), "l"(b), "l"(c)); return r;
}
__device__ __forceinline__ float ex2a(float x) {
    float r; asm("ex2.approx.ftz.f32 %0, %1;" : "=f"(r) : "f"(x)); return r;
}
__device__ __forceinline__ float rsqa(float x) {
    float r; asm("rsqrt.approx.ftz.f32 %0, %1;" : "=f"(r) : "f"(x)); return r;
}

__device__ __forceinline__ float4 integrate(float4 s, float2 g, float2 rf, float des) {
    float tx = g.x - s.x, ty = g.y - s.y;
    float dist = sqrtf(fmaf(tx, tx, fmaf(ty, ty, EPSF)));
    float k = des / dist;
    float Fx = rf.x + 2.0f * (tx * k - s.z);         // K = 2
    float Fy = rf.y + 2.0f * (ty * k - s.w);
    float vx = fmaf(Fx, 0.1f / 60.0f, s.z);          // vel + F/mass*dt
    float vy = fmaf(Fy, 0.1f / 60.0f, s.w);
    float sp = sqrtf(fmaf(vx, vx, fmaf(vy, vy, EPSF)));
    float sc = fminf(1.0f, 1.4f / sp);
    vx *= sc; vy *= sc;
    return make_float4(fmaf(vx, 0.1f, s.x), fmaf(vy, 0.1f, s.y), vx, vy);
}

// ---------------------------------------------------------------------------
// ONE kernel: pairwise forces (all 592 blocks) + device-wide arrive counter +
// inline epilogue (the 16 blocks with blockIdx.y==0).
//
// Pair math: mag/d = 10*exp((0.6-d)/0.71)/d = exp2(fma(d,-C1,C0))/d
//   C1 = log2(e)/0.71 = 2.0319649, C0 = 0.6*C1 + log2(10) = 4.5411070
// Diagonal j==i: dx=dy=0 -> contribution exactly 0. Sentinel j>=NN: pos -1e9
// -> exp2(huge negative) = 0. Alternating duos balance MUFU vs FMA pipes
// (even duo: MUFU.RSQ; odd duo: magic-int + 1 packed Newton).
// ---------------------------------------------------------------------------
__global__ __launch_bounds__(IBLK, 4) void sim_kernel(const float4* __restrict__ state,
                                                      const float2* __restrict__ goals,
                                                      const float* __restrict__ cost_in,
                                                      const float* __restrict__ rip,
                                                      const float* __restrict__ goal,
                                                      float4* __restrict__ out,
                                                      float* __restrict__ cost_out) {
    __shared__ u64 snx[NDUO], sny[NDUO];   // NEGATED packed j positions

    const int i     = blockIdx.x * IBLK + threadIdx.x;
    const int jbase = blockIdx.y * JCH;

    if (threadIdx.x < NDUO) {
        int j0 = jbase + 2 * threadIdx.x;
        float x0 = 1e9f, y0 = 1e9f, x1 = 1e9f, y1 = 1e9f;
        if (j0 < NN)     { float4 s = state[j0];     x0 = -s.x; y0 = -s.y; }
        if (j0 + 1 < NN) { float4 s = state[j0 + 1]; x1 = -s.x; y1 = -s.y; }
        snx[threadIdx.x] = pk2(x0, x1);
        sny[threadIdx.x] = pk2(y0, y1);
    }
    __syncthreads();

    const float4 si = state[i];
    const u64 xi2   = pk2(si.x, si.x);
    const u64 yi2   = pk2(si.y, si.y);
    const u64 eps2  = pk2(EPSF, EPSF);
    const u64 nC1_2 = pk2(-2.0319649f, -2.0319649f);
    const u64 C0_2  = pk2(4.5411070f, 4.5411070f);
    const u64 nh2   = pk2(-0.5f, -0.5f);
    const u64 c1p5  = pk2(1.5f, 1.5f);

    u64 fx2 = pk2(0.0f, 0.0f);
    u64 fy2 = fx2;

#pragma unroll 4
    for (int jj = 0; jj < NDUO; jj += 2) {
        {   // duo A: MUFU rsqrt path
            u64 dx = add2(xi2, snx[jj]);
            u64 dy = add2(yi2, sny[jj]);
            u64 t  = fma2(dx, dx, eps2);
            t      = fma2(dy, dy, t);
            float t0, t1; upk2(t, t0, t1);
            u64 inv = pk2(rsqa(t0), rsqa(t1));
            u64 d   = mul2(t, inv);
            u64 arg = fma2(d, nC1_2, C0_2);
            float a0, a1; upk2(arg, a0, a1);
            u64 e = pk2(ex2a(a0), ex2a(a1));
            u64 s = mul2(e, inv);
            fx2 = fma2(s, dx, fx2);
            fy2 = fma2(s, dy, fy2);
        }
        {   // duo B: soft rsqrt (magic + 1 packed Newton) -> frees MUFU pipe
            u64 dx = add2(xi2, snx[jj + 1]);
            u64 dy = add2(yi2, sny[jj + 1]);
            u64 t  = fma2(dx, dx, eps2);
            t      = fma2(dy, dy, t);
            float t0, t1; upk2(t, t0, t1);
            float g0 = __uint_as_float(0x5F3759DFu - (__float_as_uint(t0) >> 1));
            float g1 = __uint_as_float(0x5F3759DFu - (__float_as_uint(t1) >> 1));
            u64 y = pk2(g0, g1);
            u64 p = mul2(mul2(t, nh2), y);
            u64 q = fma2(p, y, c1p5);
            u64 inv = mul2(y, q);
            u64 d   = mul2(t, inv);
            u64 arg = fma2(d, nC1_2, C0_2);
            float a0, a1; upk2(arg, a0, a1);
            u64 e = pk2(ex2a(a0), ex2a(a1));
            u64 s = mul2(e, inv);
            fx2 = fma2(s, dx, fx2);
            fy2 = fma2(s, dy, fy2);
        }
    }

    float lo, hi;
    upk2(fx2, lo, hi); float pfx = lo + hi;
    upk2(fy2, lo, hi); float pfy = lo + hi;
    g_rf[blockIdx.y][i] = make_float2(pfx, pfy);

    // ---- publish partial, arrive ----
    __syncthreads();                       // all block stores done (cta scope)
    if (threadIdx.x == 0) {
        __threadfence();                   // promote to gpu scope
        atomicAdd(&g_arrive, 1u);
    }
    if (blockIdx.y != 0) return;

    // ---- epilogue: 16 blocks, one agent per thread (same i as pair phase) --
    if (threadIdx.x == 0) {
        while (atomicAdd(&g_arrive, 0u) < NBLK) __nanosleep(64);
        __threadfence();
    }
    __syncthreads();

    float fx = 0.0f, fy = 0.0f, r0x = 0.0f, r0y = 0.0f;
#pragma unroll 8
    for (int c = 0; c < NJC; c++) {
        float2 p = g_rf[c][i];             // coalesced 256B per warp
        fx += p.x; fy += p.y;
        float2 q = g_rf[c][0];             // broadcast (L1/L2-warm, same launch)
        r0x += q.x; r0y += q.y;
    }

    float4 oi = integrate(si, goals[i], make_float2(fx, fy), (i == 0) ? 1.0f : 1.4f);
    out[i] = oi;

    // Agent-0 pose: identical summation order -> bitwise-equal to out[0].
    float4 o0 = (i == 0) ? oi : integrate(state[0], goals[0], make_float2(r0x, r0y), 1.0f);

    float gx = goal[0], gy = goal[1];
    float a0 = rip[0] - gx, a1 = rip[1] - gy;
    float b0 = o0.x - gx,  b1 = o0.y - gy;
    float pg = sqrtf(fmaf(a0, a0, fmaf(a1, a1, EPSF)))
             - sqrtf(fmaf(b0, b0, fmaf(b1, b1, EPSF)));

    float ddx = oi.x - o0.x, ddy = oi.y - o0.y;
    float dr = sqrtf(fmaf(ddx, ddx, fmaf(ddy, ddy, EPSF)));
    float e  = ex2a(dr * (-1.4426950408889634f / 1.5f));   // exp(-dr/1.5)

    cost_out[i] = cost_in[i] + fmaf(2.0f, e, 5.0f * pg);

    // ---- self-reset counters for the next (graph-replayed) invocation ----
    __syncthreads();
    if (threadIdx.x == 0) {
        unsigned d = atomicAdd(&g_done, 1u);
        if (d == 15u) {                    // last epilogue block: all spins passed
            g_arrive = 0u;
            g_done   = 0u;
            __threadfence();
        }
    }
}

// ---------------------------------------------------------------------------
// Inputs (metadata order): state[N,4], cost[N,1], goals[N,2],
// robot_init_pose[2], goal[2]. Output: out[N,4] then new_cost[N,1].
// ---------------------------------------------------------------------------
extern "C" void kernel_launch(void* const* d_in, const int* in_sizes, int n_in,
                              void* d_out, int out_size) {
    const float* state = (const float*)d_in[0];
    const float* cost  = (const float*)d_in[1];
    const float* goals = (const float*)d_in[2];
    const float* rip   = (const float*)d_in[3];
    const float* goal  = (const float*)d_in[4];
    float* out = (float*)d_out;

    dim3 grid(NN / IBLK, NJC);             // 16 x 37 = 592 blocks = 4/SM, one wave
    sim_kernel<<<grid, IBLK>>>((const float4*)state, (const float2*)goals,
                               cost, rip, goal,
                               (float4*)out, out + NN * 4);
}

// round 7
// speedup vs baseline: 1.1215x; 1.1215x over previous
#include <cuda_runtime.h>

#define NN 4096
#define NJC 37                // j-chunks (grid.y); 16*37 = 592 blocks = 4/SM one wave
#define JCH 112               // j's per chunk (37*112 = 4144 >= 4096, rest sentinels)
#define NDUO (JCH / 2)        // 56 packed duos per chunk
#define IBLK 256
#define NBLK (16 * NJC)       // 592 blocks
#define RFPAD 40              // padded row length (37 chunks + pad)
#define APB 7                 // agents per block in epilogue (592*7 = 4144 >= 4096)
#define EPSF 1e-8f

// Transposed partials: g_rfT[agent][chunk] -> epilogue lane loads are contiguous.
__device__ float2 g_rfT[NN][RFPAD];
// Grid-sync counters (threadFenceReduction pattern); self-reset each run.
__device__ unsigned g_arrive;
__device__ unsigned g_done;

typedef unsigned long long u64;

// ---- packed f32x2 helpers (sm_103a) --------------------------------------
__device__ __forceinline__ u64 pk2(float lo, float hi) {
    u64 r; asm("mov.b64 %0, {%1, %2};" : "=l"(r) : "f"(lo), "f"(hi)); return r;
}
__device__ __forceinline__ void upk2(u64 v, float& lo, float& hi) {
    asm("mov.b64 {%0, %1}, %2;" : "=f"(lo), "=f"(hi) : "l"(v));
}
__device__ __forceinline__ u64 add2(u64 a, u64 b) {
    u64 r; asm("add.rn.f32x2 %0, %1, %2;" : "=l"(r) : "l"(a), "l"(b)); return r;
}
__device__ __forceinline__ u64 mul2(u64 a, u64 b) {
    u64 r; asm("mul.rn.f32x2 %0, %1, %2;" : "=l"(r) : "l"(a), "l"(b)); return r;
}
__device__ __forceinline__ u64 fma2(u64 a, u64 b, u64 c) {
    u64 r; asm("fma.rn.f32x2 %0, %1, %2, %3;" : "=l"(r) : "l"(a), "l"(b), "l"(c)); return r;
}
__device__ __forceinline__ float ex2a(float x) {
    float r; asm("ex2.approx.ftz.f32 %0, %1;" : "=f"(r) : "f"(x)); return r;
}
__device__ __forceinline__ float rsqa(float x) {
    float r; asm("rsqrt.approx.ftz.f32 %0, %1;" : "=f"(r) : "f"(x)); return r;
}

__device__ __forceinline__ float4 integrate(float4 s, float2 g, float fx, float fy, float des) {
    float tx = g.x - s.x, ty = g.y - s.y;
    float dist = sqrtf(fmaf(tx, tx, fmaf(ty, ty, EPSF)));
    float k = des / dist;
    float Fx = fx + 2.0f * (tx * k - s.z);           // K = 2
    float Fy = fy + 2.0f * (ty * k - s.w);
    float vx = fmaf(Fx, 0.1f / 60.0f, s.z);          // vel + F/mass*dt
    float vy = fmaf(Fy, 0.1f / 60.0f, s.w);
    float sp = sqrtf(fmaf(vx, vx, fmaf(vy, vy, EPSF)));
    float sc = fminf(1.0f, 1.4f / sp);
    vx *= sc; vy *= sc;
    return make_float4(fmaf(vx, 0.1f, s.x), fmaf(vy, 0.1f, s.y), vx, vy);
}

// ---------------------------------------------------------------------------
// ONE kernel, one wave (592 blocks = 4/SM):
//  phase 1: all blocks compute pairwise-force partials (f32x2, pipe-balanced)
//  grid-sync via arrive counter (all blocks resident -> no deadlock)
//  phase 2: ALL blocks do the epilogue; block owns 7 agents, one per warp,
//           warp-shuffle reduction over 37 chunks (coalesced via g_rfT).
// mag/d = 10*exp((0.6-d)/0.71)/d = exp2(fma(d,-C1,C0))/d
//   C1 = log2(e)/0.71 = 2.0319649, C0 = 0.6*C1 + log2(10) = 4.5411070
// Diagonal j==i contributes exactly 0; sentinel j>=NN -> exp2(-huge)=0.
// ---------------------------------------------------------------------------
__global__ __launch_bounds__(IBLK, 4) void sim_kernel(const float4* __restrict__ state,
                                                      const float2* __restrict__ goals,
                                                      const float* __restrict__ cost_in,
                                                      const float* __restrict__ rip,
                                                      const float* __restrict__ goal,
                                                      float4* __restrict__ out,
                                                      float* __restrict__ cost_out) {
    __shared__ u64 snx[NDUO], sny[NDUO];   // NEGATED packed j positions

    const int i     = blockIdx.x * IBLK + threadIdx.x;
    const int jbase = blockIdx.y * JCH;

    if (threadIdx.x < NDUO) {
        int j0 = jbase + 2 * threadIdx.x;
        float x0 = 1e9f, y0 = 1e9f, x1 = 1e9f, y1 = 1e9f;
        if (j0 < NN)     { float4 s = state[j0];     x0 = -s.x; y0 = -s.y; }
        if (j0 + 1 < NN) { float4 s = state[j0 + 1]; x1 = -s.x; y1 = -s.y; }
        snx[threadIdx.x] = pk2(x0, x1);
        sny[threadIdx.x] = pk2(y0, y1);
    }
    __syncthreads();

    {
        const float4 si = state[i];
        const u64 xi2   = pk2(si.x, si.x);
        const u64 yi2   = pk2(si.y, si.y);
        const u64 eps2  = pk2(EPSF, EPSF);
        const u64 nC1_2 = pk2(-2.0319649f, -2.0319649f);
        const u64 C0_2  = pk2(4.5411070f, 4.5411070f);
        const u64 nh2   = pk2(-0.5f, -0.5f);
        const u64 c1p5  = pk2(1.5f, 1.5f);

        u64 fx2 = pk2(0.0f, 0.0f);
        u64 fy2 = fx2;

#pragma unroll 4
        for (int jj = 0; jj < NDUO; jj += 2) {
            {   // duo A: MUFU rsqrt path
                u64 dx = add2(xi2, snx[jj]);
                u64 dy = add2(yi2, sny[jj]);
                u64 t  = fma2(dx, dx, eps2);
                t      = fma2(dy, dy, t);
                float t0, t1; upk2(t, t0, t1);
                u64 inv = pk2(rsqa(t0), rsqa(t1));
                u64 d   = mul2(t, inv);
                u64 arg = fma2(d, nC1_2, C0_2);
                float a0, a1; upk2(arg, a0, a1);
                u64 e = pk2(ex2a(a0), ex2a(a1));
                u64 s = mul2(e, inv);
                fx2 = fma2(s, dx, fx2);
                fy2 = fma2(s, dy, fy2);
            }
            {   // duo B: soft rsqrt (magic + 1 packed Newton) -> frees MUFU
                u64 dx = add2(xi2, snx[jj + 1]);
                u64 dy = add2(yi2, sny[jj + 1]);
                u64 t  = fma2(dx, dx, eps2);
                t      = fma2(dy, dy, t);
                float t0, t1; upk2(t, t0, t1);
                float g0 = __uint_as_float(0x5F3759DFu - (__float_as_uint(t0) >> 1));
                float g1 = __uint_as_float(0x5F3759DFu - (__float_as_uint(t1) >> 1));
                u64 y = pk2(g0, g1);
                u64 p = mul2(mul2(t, nh2), y);
                u64 q = fma2(p, y, c1p5);
                u64 inv = mul2(y, q);
                u64 d   = mul2(t, inv);
                u64 arg = fma2(d, nC1_2, C0_2);
                float a0, a1; upk2(arg, a0, a1);
                u64 e = pk2(ex2a(a0), ex2a(a1));
                u64 s = mul2(e, inv);
                fx2 = fma2(s, dx, fx2);
                fy2 = fma2(s, dy, fy2);
            }
        }

        float lo, hi;
        upk2(fx2, lo, hi); float pfx = lo + hi;
        upk2(fy2, lo, hi); float pfy = lo + hi;
        g_rfT[i][blockIdx.y] = make_float2(pfx, pfy);
    }

    // ---- grid sync: publish partials, arrive, wait ----
    __threadfence();
    __syncthreads();
    if (threadIdx.x == 0) {
        atomicAdd(&g_arrive, 1u);
        while (atomicAdd(&g_arrive, 0u) < NBLK) __nanosleep(32);
    }
    __syncthreads();
    __threadfence();

    // ---- distributed epilogue: 7 agents per block, one per warp ----
    const int lane = threadIdx.x & 31;
    const int w    = threadIdx.x >> 5;
    const int bid  = blockIdx.y * 16 + blockIdx.x;
    const int a    = bid * APB + w;

    if (w < APB && a < NN) {
        // lane l sums chunks c = l and c = l + 32 (l < 5), for agent a AND agent 0
        float fx, fy, r0x, r0y;
        {
            float2 p = g_rfT[a][lane];
            float2 q = g_rfT[0][lane];
            fx = p.x; fy = p.y; r0x = q.x; r0y = q.y;
            if (lane < NJC - 32) {
                float2 p2 = g_rfT[a][lane + 32];
                float2 q2 = g_rfT[0][lane + 32];
                fx += p2.x; fy += p2.y; r0x += q2.x; r0y += q2.y;
            }
        }
#pragma unroll
        for (int off = 16; off > 0; off >>= 1) {
            fx  += __shfl_down_sync(0xFFFFFFFFu, fx,  off);
            fy  += __shfl_down_sync(0xFFFFFFFFu, fy,  off);
            r0x += __shfl_down_sync(0xFFFFFFFFu, r0x, off);
            r0y += __shfl_down_sync(0xFFFFFFFFu, r0y, off);
        }

        if (lane == 0) {
            float4 oi = integrate(state[a], goals[a], fx, fy, (a == 0) ? 1.0f : 1.4f);
            out[a] = oi;

            // Agent-0 pose via the IDENTICAL shuffle-tree order -> bitwise == out[0].
            float4 o0 = (a == 0) ? oi : integrate(state[0], goals[0], r0x, r0y, 1.0f);

            float gx = goal[0], gy = goal[1];
            float a0 = rip[0] - gx, a1 = rip[1] - gy;
            float b0 = o0.x - gx,  b1 = o0.y - gy;
            float pg = sqrtf(fmaf(a0, a0, fmaf(a1, a1, EPSF)))
                     - sqrtf(fmaf(b0, b0, fmaf(b1, b1, EPSF)));

            float ddx = oi.x - o0.x, ddy = oi.y - o0.y;
            float dr = sqrtf(fmaf(ddx, ddx, fmaf(ddy, ddy, EPSF)));
            float e  = ex2a(dr * (-1.4426950408889634f / 1.5f));   // exp(-dr/1.5)

            cost_out[a] = cost_in[a] + fmaf(2.0f, e, 5.0f * pg);
        }
    }

    // ---- self-reset counters for the next graph replay ----
    __syncthreads();
    if (threadIdx.x == 0) {
        unsigned d = atomicAdd(&g_done, 1u);
        if (d == NBLK - 1u) {              // last block: every spin has passed
            g_arrive = 0u;
            g_done   = 0u;
            __threadfence();
        }
    }
}

// ---------------------------------------------------------------------------
// Inputs (metadata order): state[N,4], cost[N,1], goals[N,2],
// robot_init_pose[2], goal[2]. Output: out[N,4] then new_cost[N,1].
// ---------------------------------------------------------------------------
extern "C" void kernel_launch(void* const* d_in, const int* in_sizes, int n_in,
                              void* d_out, int out_size) {
    const float* state = (const float*)d_in[0];
    const float* cost  = (const float*)d_in[1];
    const float* goals = (const float*)d_in[2];
    const float* rip   = (const float*)d_in[3];
    const float* goal  = (const float*)d_in[4];
    float* out = (float*)d_out;

    dim3 grid(NN / IBLK, NJC);             // 16 x 37 = 592 blocks = 4/SM, one wave
    sim_kernel<<<grid, IBLK>>>((const float4*)state, (const float2*)goals,
                               cost, rip, goal,
                               (float4*)out, out + NN * 4);
}

// round 8
// speedup vs baseline: 1.1364x; 1.0133x over previous
#include <cuda_runtime.h>

#define NN 4096
#define NJC 37                // j-chunks (grid.y); 16*37 = 592 blocks = 4/SM one wave
#define JCH 112               // j's per chunk (37*112 = 4144 >= 4096, rest sentinels)
#define NDUO (JCH / 2)        // 56 packed duos per chunk
#define IBLK 256
#define NBLK (16 * NJC)       // 592 blocks
#define RFPAD 40              // padded row length (37 chunks + pad)
#define APB 7                 // agents per block in epilogue (592*7 = 4144 >= 4096)
#define EPSF 1e-8f

// Transposed partials: g_rfT[agent][chunk] -> epilogue lane loads contiguous.
__device__ float2 g_rfT[NN][RFPAD];
// Grid-sync counters; self-reset each run -> deterministic graph replays.
__device__ unsigned g_arrive;
__device__ unsigned g_done;

typedef unsigned long long u64;

// ---- packed f32x2 helpers (sm_103a) --------------------------------------
__device__ __forceinline__ u64 pk2(float lo, float hi) {
    u64 r; asm("mov.b64 %0, {%1, %2};" : "=l"(r) : "f"(lo), "f"(hi)); return r;
}
__device__ __forceinline__ void upk2(u64 v, float& lo, float& hi) {
    asm("mov.b64 {%0, %1}, %2;" : "=f"(lo), "=f"(hi) : "l"(v));
}
__device__ __forceinline__ u64 add2(u64 a, u64 b) {
    u64 r; asm("add.rn.f32x2 %0, %1, %2;" : "=l"(r) : "l"(a), "l"(b)); return r;
}
__device__ __forceinline__ u64 mul2(u64 a, u64 b) {
    u64 r; asm("mul.rn.f32x2 %0, %1, %2;" : "=l"(r) : "l"(a), "l"(b)); return r;
}
__device__ __forceinline__ u64 fma2(u64 a, u64 b, u64 c) {
    u64 r; asm("fma.rn.f32x2 %0, %1, %2, %3;" : "=l"(r) : "l"(a), "l"(b), "l"(c)); return r;
}
__device__ __forceinline__ float ex2a(float x) {
    float r; asm("ex2.approx.ftz.f32 %0, %1;" : "=f"(r) : "f"(x)); return r;
}
__device__ __forceinline__ float rsqa(float x) {
    float r; asm("rsqrt.approx.ftz.f32 %0, %1;" : "=f"(r) : "f"(x)); return r;
}

__device__ __forceinline__ float4 integrate(float4 s, float2 g, float fx, float fy, float des) {
    float tx = g.x - s.x, ty = g.y - s.y;
    float dist = sqrtf(fmaf(tx, tx, fmaf(ty, ty, EPSF)));
    float k = des / dist;
    float Fx = fx + 2.0f * (tx * k - s.z);           // K = 2
    float Fy = fy + 2.0f * (ty * k - s.w);
    float vx = fmaf(Fx, 0.1f / 60.0f, s.z);          // vel + F/mass*dt
    float vy = fmaf(Fy, 0.1f / 60.0f, s.w);
    float sp = sqrtf(fmaf(vx, vx, fmaf(vy, vy, EPSF)));
    float sc = fminf(1.0f, 1.4f / sp);
    vx *= sc; vy *= sc;
    return make_float4(fmaf(vx, 0.1f, s.x), fmaf(vy, 0.1f, s.y), vx, vy);
}

// ---------------------------------------------------------------------------
// ONE kernel, one wave (592 blocks = 4/SM):
//  phase 1: pairwise-force partials (f32x2, MUFU/FMA balanced)
//  grid sync: red.release arrive + ld.acquire READ-polling (no RMW spin!)
//  phase 2: distributed epilogue, 7 agents/block, warp-shuffle reduction.
// mag/d = 10*exp((0.6-d)/0.71)/d = exp2(fma(d,-C1,C0))/d
//   C1 = log2(e)/0.71 = 2.0319649, C0 = 0.6*C1 + log2(10) = 4.5411070
// Diagonal j==i contributes exactly 0; sentinel j>=NN -> exp2(-huge)=0.
// ---------------------------------------------------------------------------
__global__ __launch_bounds__(IBLK, 4) void sim_kernel(const float4* __restrict__ state,
                                                      const float2* __restrict__ goals,
                                                      const float* __restrict__ cost_in,
                                                      const float* __restrict__ rip,
                                                      const float* __restrict__ goal,
                                                      float4* __restrict__ out,
                                                      float* __restrict__ cost_out) {
    __shared__ u64 snx[NDUO], sny[NDUO];   // NEGATED packed j positions

    const int i     = blockIdx.x * IBLK + threadIdx.x;
    const int jbase = blockIdx.y * JCH;

    if (threadIdx.x < NDUO) {
        int j0 = jbase + 2 * threadIdx.x;
        float x0 = 1e9f, y0 = 1e9f, x1 = 1e9f, y1 = 1e9f;
        if (j0 < NN)     { float4 s = state[j0];     x0 = -s.x; y0 = -s.y; }
        if (j0 + 1 < NN) { float4 s = state[j0 + 1]; x1 = -s.x; y1 = -s.y; }
        snx[threadIdx.x] = pk2(x0, x1);
        sny[threadIdx.x] = pk2(y0, y1);
    }
    __syncthreads();

    {
        const float4 si = state[i];
        const u64 xi2   = pk2(si.x, si.x);
        const u64 yi2   = pk2(si.y, si.y);
        const u64 eps2  = pk2(EPSF, EPSF);
        const u64 nC1_2 = pk2(-2.0319649f, -2.0319649f);
        const u64 C0_2  = pk2(4.5411070f, 4.5411070f);
        const u64 nh2   = pk2(-0.5f, -0.5f);
        const u64 c1p5  = pk2(1.5f, 1.5f);

        u64 fx2 = pk2(0.0f, 0.0f);
        u64 fy2 = fx2;

#pragma unroll 4
        for (int jj = 0; jj < NDUO; jj += 2) {
            {   // duo A: MUFU rsqrt path
                u64 dx = add2(xi2, snx[jj]);
                u64 dy = add2(yi2, sny[jj]);
                u64 t  = fma2(dx, dx, eps2);
                t      = fma2(dy, dy, t);
                float t0, t1; upk2(t, t0, t1);
                u64 inv = pk2(rsqa(t0), rsqa(t1));
                u64 d   = mul2(t, inv);
                u64 arg = fma2(d, nC1_2, C0_2);
                float a0, a1; upk2(arg, a0, a1);
                u64 e = pk2(ex2a(a0), ex2a(a1));
                u64 s = mul2(e, inv);
                fx2 = fma2(s, dx, fx2);
                fy2 = fma2(s, dy, fy2);
            }
            {   // duo B: soft rsqrt (magic + 1 packed Newton) -> frees MUFU
                u64 dx = add2(xi2, snx[jj + 1]);
                u64 dy = add2(yi2, sny[jj + 1]);
                u64 t  = fma2(dx, dx, eps2);
                t      = fma2(dy, dy, t);
                float t0, t1; upk2(t, t0, t1);
                float g0 = __uint_as_float(0x5F3759DFu - (__float_as_uint(t0) >> 1));
                float g1 = __uint_as_float(0x5F3759DFu - (__float_as_uint(t1) >> 1));
                u64 y = pk2(g0, g1);
                u64 p = mul2(mul2(t, nh2), y);
                u64 q = fma2(p, y, c1p5);
                u64 inv = mul2(y, q);
                u64 d   = mul2(t, inv);
                u64 arg = fma2(d, nC1_2, C0_2);
                float a0, a1; upk2(arg, a0, a1);
                u64 e = pk2(ex2a(a0), ex2a(a1));
                u64 s = mul2(e, inv);
                fx2 = fma2(s, dx, fx2);
                fy2 = fma2(s, dy, fy2);
            }
        }

        float lo, hi;
        upk2(fx2, lo, hi); float pfx = lo + hi;
        upk2(fy2, lo, hi); float pfy = lo + hi;
        g_rfT[i][blockIdx.y] = make_float2(pfx, pfy);
    }

    // ---- grid sync: release-arrive, then READ-poll (no atomic-RMW spin) ----
    __syncthreads();                        // all block stores issued
    if (threadIdx.x == 0) {
        __threadfence();                    // gpu-scope visibility of g_rfT
        asm volatile("red.release.gpu.global.add.u32 [%0], 1;"
                     :: "l"(&g_arrive) : "memory");
        unsigned v;
        do {
            __nanosleep(128);
            asm volatile("ld.acquire.gpu.global.u32 %0, [%1];"
                         : "=r"(v) : "l"(&g_arrive) : "memory");
        } while (v < NBLK);
    }
    __syncthreads();                        // broadcast acquire to whole block

    // ---- distributed epilogue: 7 agents per block, one per warp ----
    const int lane = threadIdx.x & 31;
    const int w    = threadIdx.x >> 5;
    const int bid  = blockIdx.y * 16 + blockIdx.x;
    const int a    = bid * APB + w;

    if (w < APB && a < NN) {
        // lane l sums chunks c = l and c = l + 32 (l < 5), agent a AND agent 0
        float fx, fy, r0x, r0y;
        {
            float2 p = g_rfT[a][lane];
            float2 q = g_rfT[0][lane];
            fx = p.x; fy = p.y; r0x = q.x; r0y = q.y;
            if (lane < NJC - 32) {
                float2 p2 = g_rfT[a][lane + 32];
                float2 q2 = g_rfT[0][lane + 32];
                fx += p2.x; fy += p2.y; r0x += q2.x; r0y += q2.y;
            }
        }
#pragma unroll
        for (int off = 16; off > 0; off >>= 1) {
            fx  += __shfl_down_sync(0xFFFFFFFFu, fx,  off);
            fy  += __shfl_down_sync(0xFFFFFFFFu, fy,  off);
            r0x += __shfl_down_sync(0xFFFFFFFFu, r0x, off);
            r0y += __shfl_down_sync(0xFFFFFFFFu, r0y, off);
        }

        if (lane == 0) {
            float4 oi = integrate(state[a], goals[a], fx, fy, (a == 0) ? 1.0f : 1.4f);
            out[a] = oi;

            // Agent-0 pose via IDENTICAL shuffle-tree order -> bitwise == out[0].
            float4 o0 = (a == 0) ? oi : integrate(state[0], goals[0], r0x, r0y, 1.0f);

            float gx = goal[0], gy = goal[1];
            float a0 = rip[0] - gx, a1 = rip[1] - gy;
            float b0 = o0.x - gx,  b1 = o0.y - gy;
            float pg = sqrtf(fmaf(a0, a0, fmaf(a1, a1, EPSF)))
                     - sqrtf(fmaf(b0, b0, fmaf(b1, b1, EPSF)));

            float ddx = oi.x - o0.x, ddy = oi.y - o0.y;
            float dr = sqrtf(fmaf(ddx, ddx, fmaf(ddy, ddy, EPSF)));
            float e  = ex2a(dr * (-1.4426950408889634f / 1.5f));  // exp(-dr/1.5)

            cost_out[a] = cost_in[a] + fmaf(2.0f, e, 5.0f * pg);
        }
    }

    // ---- self-reset counters for the next graph replay (no polling) ----
    __syncthreads();
    if (threadIdx.x == 0) {
        unsigned d = atomicAdd(&g_done, 1u);
        if (d == NBLK - 1u) {              // last block: every wait has passed
            g_arrive = 0u;
            g_done   = 0u;
            __threadfence();
        }
    }
}

// ---------------------------------------------------------------------------
// Inputs (metadata order): state[N,4], cost[N,1], goals[N,2],
// robot_init_pose[2], goal[2]. Output: out[N,4] then new_cost[N,1].
// ---------------------------------------------------------------------------
extern "C" void kernel_launch(void* const* d_in, const int* in_sizes, int n_in,
                              void* d_out, int out_size) {
    const float* state = (const float*)d_in[0];
    const float* cost  = (const float*)d_in[1];
    const float* goals = (const float*)d_in[2];
    const float* rip   = (const float*)d_in[3];
    const float* goal  = (const float*)d_in[4];
    float* out = (float*)d_out;

    dim3 grid(NN / IBLK, NJC);             // 16 x 37 = 592 blocks = 4/SM, one wave
    sim_kernel<<<grid, IBLK>>>((const float4*)state, (const float2*)goals,
                               cost, rip, goal,
                               (float4*)out, out + NN * 4);
}